// round 1
// baseline (speedup 1.0000x reference)
#include <cuda_runtime.h>

#define NH    16
#define NK    8
#define D_IN  1024
#define D_H   64
#define D_O   64
#define MT    128

// scratch for scores (allocation-free rule: __device__ global)
__device__ float g_scores[8192 * NK];

__device__ __forceinline__ unsigned long long fma2(unsigned long long a,
                                                   unsigned long long b,
                                                   unsigned long long c) {
    unsigned long long d;
    asm("fma.rn.f32x2 %0, %1, %2, %3;" : "=l"(d) : "l"(a), "l"(b), "l"(c));
    return d;
}
__device__ __forceinline__ unsigned long long splat2(float x) {
    unsigned long long d;
    asm("mov.b64 %0, {%1, %1};" : "=l"(d) : "f"(x));
    return d;
}

// ---------------------------------------------------------------------------
// Kernel 1: scores[m,k] = phi[t,k] + sum_i x[m,i] * diag[k,i]
// 1 warp per token, 8 tokens per 256-thread block.
// ---------------------------------------------------------------------------
__global__ __launch_bounds__(256) void scores_kernel(
        const float* __restrict__ x,
        const float* __restrict__ diag,
        const float* __restrict__ phi,
        int M, int T) {
    __shared__ float sdiag[NK * D_IN];
    int tid = threadIdx.x;
    for (int idx = tid; idx < NK * D_IN / 4; idx += 256)
        ((float4*)sdiag)[idx] = ((const float4*)diag)[idx];
    __syncthreads();

    int warp = tid >> 5, lane = tid & 31;
    int m = blockIdx.x * 8 + warp;
    if (m >= M) return;

    const float4* xr = (const float4*)(x + (size_t)m * D_IN);
    float acc[NK];
#pragma unroll
    for (int k = 0; k < NK; k++) acc[k] = 0.f;

#pragma unroll
    for (int j = 0; j < 8; j++) {
        float4 xv = xr[j * 32 + lane];
#pragma unroll
        for (int k = 0; k < NK; k++) {
            float4 dv = *(const float4*)&sdiag[k * D_IN + j * 128 + lane * 4];
            acc[k] += xv.x * dv.x + xv.y * dv.y + xv.z * dv.z + xv.w * dv.w;
        }
    }
#pragma unroll
    for (int k = 0; k < NK; k++) {
#pragma unroll
        for (int off = 16; off; off >>= 1)
            acc[k] += __shfl_xor_sync(0xffffffffu, acc[k], off);
    }
    if (lane < NK) {
        float v = 0.f;
#pragma unroll
        for (int k = 0; k < NK; k++)
            if (lane == k) v = acc[k];
        int t = m % T;
        g_scores[m * NK + lane] = phi[t * NK + lane] + v;
    }
}

// ---------------------------------------------------------------------------
// Kernel 2: per (token-tile, head) block.
//   z[m,o] (chunk k) = sum_i x[m, h*64+i] * W[h,k,i,o]
//   acc[m,o] += scores[m,k] * z[m,o]
// smem: W[h] as [i][k*64+o] (128 KB), x-tile transposed [i][row] (33 KB),
//       scores as [k][row] (4 KB). f32x2 packed FMA throughout.
// ---------------------------------------------------------------------------
#define WS_FLOATS   (D_H * NK * D_O)        /* 64*512 = 32768 */
#define XST_STRIDE  132                     /* 128 + 4 pad: conflict-free */
#define XST_FLOATS  (D_H * XST_STRIDE)      /* 8448 */
#define SS_FLOATS   (NK * MT)               /* 1024 */
#define SMEM_BYTES  ((WS_FLOATS + XST_FLOATS + SS_FLOATS) * 4)

__global__ __launch_bounds__(256, 1) void main_kernel(
        const float* __restrict__ x,
        const float* __restrict__ weight,
        float* __restrict__ out) {
    extern __shared__ float sm[];
    float* Ws  = sm;                         // [i][k*64+o]
    float* xsT = sm + WS_FLOATS;             // [i][row], stride 132
    float* ss  = xsT + XST_FLOATS;           // [k][row]

    int tid = threadIdx.x;
    int h   = blockIdx.y;
    int m0  = blockIdx.x * MT;

    // --- fill W[h]: gmem [k][i][o] -> smem [i][k*64+o]
    {
        const float4* wg = (const float4*)(weight + (size_t)h * (NK * D_H * D_O));
        for (int idx = tid; idx < WS_FLOATS / 4; idx += 256) {
            int v = idx * 4;
            int k = v >> 12;          // /(64*64)
            int i = (v >> 6) & 63;
            int o = v & 63;
            *(float4*)&Ws[i * 512 + k * 64 + o] = wg[idx];
        }
    }
    // --- fill x tile transposed: xsT[i][r] = x[m0+r][h*64+i]
    {
        for (int idx = tid; idx < MT * 16; idx += 256) {
            int r  = idx >> 4;
            int c4 = idx & 15;
            float4 v = *(const float4*)(x + (size_t)(m0 + r) * D_IN + h * D_H + c4 * 4);
            int i = c4 * 4;
            xsT[(i + 0) * XST_STRIDE + r] = v.x;
            xsT[(i + 1) * XST_STRIDE + r] = v.y;
            xsT[(i + 2) * XST_STRIDE + r] = v.z;
            xsT[(i + 3) * XST_STRIDE + r] = v.w;
        }
    }
    // --- fill scores tile: ss[k][r] = g_scores[m0+r][k]
    {
        for (int idx = tid; idx < MT * NK; idx += 256) {
            int r = idx >> 3;
            int k = idx & 7;
            ss[k * MT + r] = g_scores[(size_t)(m0 + r) * NK + k];
        }
    }
    __syncthreads();

    int cg = tid & 7;         // 8 col-groups of 8 outputs
    int rg = tid >> 3;        // 32 row-groups of 4 rows
    int r0 = rg * 4;
    int c0 = cg * 8;

    unsigned long long acc[4][4];
#pragma unroll
    for (int a = 0; a < 4; a++)
#pragma unroll
        for (int b = 0; b < 4; b++) acc[a][b] = 0ull;

#pragma unroll 1
    for (int k = 0; k < NK; k++) {
        unsigned long long z[4][4];
#pragma unroll
        for (int a = 0; a < 4; a++)
#pragma unroll
            for (int b = 0; b < 4; b++) z[a][b] = 0ull;

        const float* xp = xsT + r0;
        const float* wp = Ws + k * 64 + c0;
#pragma unroll 4
        for (int i = 0; i < D_H; i++) {
            float4 a4 = *(const float4*)(xp + i * XST_STRIDE);
            ulonglong2 b01 = *(const ulonglong2*)(wp + i * 512);
            ulonglong2 b23 = *(const ulonglong2*)(wp + i * 512 + 4);
            float av[4] = {a4.x, a4.y, a4.z, a4.w};
            unsigned long long bv[4] = {b01.x, b01.y, b23.x, b23.y};
#pragma unroll
            for (int rr = 0; rr < 4; rr++) {
                unsigned long long aa = splat2(av[rr]);
#pragma unroll
                for (int cc = 0; cc < 4; cc++)
                    z[rr][cc] = fma2(aa, bv[cc], z[rr][cc]);
            }
        }
        // epilogue: acc += scores[:,k] * z
        float4 s4 = *(const float4*)&ss[k * MT + r0];
        float sv[4] = {s4.x, s4.y, s4.z, s4.w};
#pragma unroll
        for (int rr = 0; rr < 4; rr++) {
            unsigned long long sp = splat2(sv[rr]);
#pragma unroll
            for (int cc = 0; cc < 4; cc++)
                acc[rr][cc] = fma2(sp, z[rr][cc], acc[rr][cc]);
        }
    }

    // --- store: out[m0+r][h*64 + c0 .. c0+7]
#pragma unroll
    for (int rr = 0; rr < 4; rr++) {
        float* op = out + (size_t)(m0 + r0 + rr) * D_IN + h * D_H + c0;
        ulonglong2 v0; v0.x = acc[rr][0]; v0.y = acc[rr][1];
        ulonglong2 v1; v1.x = acc[rr][2]; v1.y = acc[rr][3];
        *(ulonglong2*)(op)     = v0;
        *(ulonglong2*)(op + 4) = v1;
    }
}

// ---------------------------------------------------------------------------
extern "C" void kernel_launch(void* const* d_in, const int* in_sizes, int n_in,
                              void* d_out, int out_size) {
    const float* x      = (const float*)d_in[0];
    const float* weight = (const float*)d_in[1];
    const float* diag   = (const float*)d_in[2];
    const float* phi    = (const float*)d_in[3];
    float* out          = (float*)d_out;

    int M = in_sizes[0] / D_IN;        // B*T tokens
    int T = in_sizes[3] / NK;          // phi rows

    cudaFuncSetAttribute(main_kernel,
                         cudaFuncAttributeMaxDynamicSharedMemorySize, SMEM_BYTES);

    scores_kernel<<<(M + 7) / 8, 256>>>(x, diag, phi, M, T);

    dim3 grid(M / MT, NH);
    main_kernel<<<grid, 256, SMEM_BYTES>>>(x, weight, out);
}